// round 7
// baseline (speedup 1.0000x reference)
#include <cuda_runtime.h>
#include <cstdint>

#define N_PTS     4096
#define N_QUERY   (64 * 552)     // 35328
#define NSAMPLE   32
#define FEAT_D    32
#define FEAT_H    64
#define K_KEYPTS  64
#define RADIUS2   4.0f
#define OUT_GROUP_OFF (K_KEYPTS * 6)
#define FULL 0xffffffffu
#define N_TILES   128            // 4096 / 32
#define N_CELLS   4096           // 16^3 Morton cells

// ---------------- device scratch (no allocs allowed) ----------------
__device__ float  g_feat[N_PTS * FEAT_D];   // tgt features (original index order)
__device__ float  g_z[N_PTS];               // src pre-softplus scores
__device__ float4 g_sp[N_PTS];              // Morton-sorted tgt xyz + ||p||^2
__device__ int    g_sidx[N_PTS];            // permuted -> original index
__device__ float4 g_tile[N_TILES];          // per-tile center (xyz) + inflated radius (w)
__device__ int    g_mort[N_PTS];            // scratch: morton code per point
__device__ int    g_pos0;                   // permuted position of original index 0

// ---------------- Kernel A: MLP for src (scores) and tgt (features) ----------------
__global__ void mlp_kernel(const float* __restrict__ src, const float* __restrict__ tgt,
                           const float* __restrict__ W1, const float* __restrict__ b1,
                           const float* __restrict__ W2, const float* __restrict__ b2,
                           const float* __restrict__ Wq, const float* __restrict__ bq)
{
    __shared__ float sW1[FEAT_H * 6], sb1[FEAT_H];
    __shared__ float sW2[FEAT_D * FEAT_H], sb2[FEAT_D], sWq[FEAT_D];
    int tid = threadIdx.x;
    for (int i = tid; i < FEAT_H * 6; i += blockDim.x) sW1[i] = W1[i];
    for (int i = tid; i < FEAT_H; i += blockDim.x)     sb1[i] = b1[i];
    for (int i = tid; i < FEAT_D * FEAT_H; i += blockDim.x) sW2[i] = W2[i];
    for (int i = tid; i < FEAT_D; i += blockDim.x)     sb2[i] = b2[i];
    for (int i = tid; i < FEAT_D; i += blockDim.x)     sWq[i] = Wq[i];
    __syncthreads();

    int n = blockIdx.x * blockDim.x + tid;
    if (n >= N_PTS) return;
    bool is_tgt = (blockIdx.y == 1);
    const float* pts = is_tgt ? tgt : src;

    float p[6];
#pragma unroll
    for (int c = 0; c < 6; c++) p[c] = pts[c * N_PTS + n];

    float facc[FEAT_D];
#pragma unroll
    for (int f = 0; f < FEAT_D; f++) facc[f] = 0.0f;

    for (int o = 0; o < FEAT_H; o++) {
        float a = 0.0f;
#pragma unroll
        for (int c = 0; c < 6; c++) a = fmaf(sW1[o * 6 + c], p[c], a);
        a += sb1[o];
        float h = fmaxf(a, 0.0f);
#pragma unroll
        for (int f = 0; f < FEAT_D; f++) facc[f] = fmaf(sW2[f * FEAT_H + o], h, facc[f]);
    }

    if (is_tgt) {
#pragma unroll
        for (int f = 0; f < FEAT_D; f++) {
            float v = fmaxf(facc[f] + sb2[f], 0.0f);
            g_feat[n * FEAT_D + f] = v;
        }
    } else {
        float z = 0.0f;
#pragma unroll
        for (int f = 0; f < FEAT_D; f++) {
            float v = fmaxf(facc[f] + sb2[f], 0.0f);
            z = fmaf(sWq[f], v, z);
        }
        z += bq[0];
        g_z[n] = z;   // softplus is monotonic -> rank on pre-activation
    }
}

// ---------------- Kernel A2: Morton counting-sort of tgt points + tile stats ----------------
__device__ __forceinline__ int morton12(int ix, int iy, int iz)
{
    int m = 0;
#pragma unroll
    for (int b = 0; b < 4; b++) {
        m |= ((ix >> b) & 1) << (3 * b + 2);
        m |= ((iy >> b) & 1) << (3 * b + 1);
        m |= ((iz >> b) & 1) << (3 * b + 0);
    }
    return m;
}

__global__ void __launch_bounds__(1024) sortstats_kernel(const float* __restrict__ tgt)
{
    __shared__ int sh_hist[N_CELLS];   // 16KB
    __shared__ int sh_wsum[32];
    int t = threadIdx.x;
    for (int i = t; i < N_CELLS; i += 1024) sh_hist[i] = 0;
    __syncthreads();

    // pass 1: morton codes + histogram
    for (int i = t; i < N_PTS; i += 1024) {
        float x = tgt[i], y = tgt[N_PTS + i], z = tgt[2 * N_PTS + i];
        int ix = min(15, max(0, (int)floorf((x + 5.0f) * 1.6f)));
        int iy = min(15, max(0, (int)floorf((y + 5.0f) * 1.6f)));
        int iz = min(15, max(0, (int)floorf((z + 5.0f) * 1.6f)));
        int m = morton12(ix, iy, iz);
        g_mort[i] = m;
        atomicAdd(&sh_hist[m], 1);
    }
    __syncthreads();

    // exclusive scan of 4096 bins (4 per thread + 2-level warp scan)
    int c0 = sh_hist[4 * t], c1 = sh_hist[4 * t + 1], c2 = sh_hist[4 * t + 2], c3 = sh_hist[4 * t + 3];
    int tsum = c0 + c1 + c2 + c3;
    int lane = t & 31, wid = t >> 5;
    int inc = tsum;
#pragma unroll
    for (int d = 1; d < 32; d <<= 1) { int y = __shfl_up_sync(FULL, inc, d); if (lane >= d) inc += y; }
    if (lane == 31) sh_wsum[wid] = inc;
    __syncthreads();
    if (t < 32) {
        int v = sh_wsum[t]; int w = v;
#pragma unroll
        for (int d = 1; d < 32; d <<= 1) { int y = __shfl_up_sync(FULL, w, d); if (t >= d) w += y; }
        sh_wsum[t] = w - v;    // exclusive warp offset
    }
    __syncthreads();
    int base = (inc - tsum) + sh_wsum[wid];   // exclusive offset for this thread's 4 bins
    sh_hist[4 * t]     = base;
    sh_hist[4 * t + 1] = base + c0;
    sh_hist[4 * t + 2] = base + c0 + c1;
    sh_hist[4 * t + 3] = base + c0 + c1 + c2;
    __syncthreads();

    // pass 2: scatter (atomic bump of per-cell start)
    for (int i = t; i < N_PTS; i += 1024) {
        float x = tgt[i], y = tgt[N_PTS + i], z = tgt[2 * N_PTS + i];
        int m = g_mort[i];
        int pos = atomicAdd(&sh_hist[m], 1);
        float px2 = __fmul_rn(x, x);
        float py2 = __fmul_rn(y, y);
        float pz2 = __fmul_rn(z, z);
        float pp  = __fadd_rn(__fadd_rn(px2, py2), pz2);
        g_sp[pos]   = make_float4(x, y, z, pp);
        g_sidx[pos] = i;
        if (i == 0) g_pos0 = pos;
    }
    __syncthreads();

    // tile stats: bbox center + inflated max radius (conservative upper bound)
    if (t < N_TILES) {
        float mnx = 1e30f, mny = 1e30f, mnz = 1e30f;
        float mxx = -1e30f, mxy = -1e30f, mxz = -1e30f;
        for (int j = 0; j < 32; j++) {
            float4 P = g_sp[t * 32 + j];
            mnx = fminf(mnx, P.x); mxx = fmaxf(mxx, P.x);
            mny = fminf(mny, P.y); mxy = fmaxf(mxy, P.y);
            mnz = fminf(mnz, P.z); mxz = fmaxf(mxz, P.z);
        }
        float cx = (mnx + mxx) * 0.5f, cy = (mny + mxy) * 0.5f, cz = (mnz + mxz) * 0.5f;
        float maxd2 = 0.0f;
        for (int j = 0; j < 32; j++) {
            float4 P = g_sp[t * 32 + j];
            float dx = P.x - cx, dy = P.y - cy, dz = P.z - cz;
            maxd2 = fmaxf(maxd2, dx * dx + dy * dy + dz * dz);
        }
        float rt = sqrtf(maxd2) * 1.0001f + 1e-5f;   // inflate => bound underestimates => safe
        g_tile[t] = make_float4(cx, cy, cz, rt);
    }
}

// ---------------- Kernel C: topk (block 0) + ball-query nearest-32 + gather ----------------
__global__ void __launch_bounds__(512)
group_kernel(const float* __restrict__ cand, const float* __restrict__ src_pts,
             float* __restrict__ out)
{
    extern __shared__ char dynsmem[];
    int tid = threadIdx.x;

    if (blockIdx.x == 0) {
        // ===== top-64 of src scores -> src_keypts (overlapped with group blocks) =====
        unsigned long long* skey = (unsigned long long*)dynsmem;  // 32KB of the 74KB
        __shared__ unsigned long long warpmax[16];
        __shared__ int sel[K_KEYPTS];

        for (int i = tid; i < N_PTS; i += 512) {
            float z = g_z[i];
            unsigned u = __float_as_uint(z);
            u = (u & 0x80000000u) ? ~u : (u | 0x80000000u);
            skey[i] = ((unsigned long long)u << 32) | (unsigned long long)(0xFFFFFFFFu - (unsigned)i);
        }
        __syncthreads();

        for (int k = 0; k < K_KEYPTS; k++) {
            unsigned long long best = 0ull;
            for (int i = tid; i < N_PTS; i += 512) {
                unsigned long long v = skey[i];
                best = (v > best) ? v : best;
            }
#pragma unroll
            for (int off = 16; off; off >>= 1) {
                unsigned long long o = __shfl_xor_sync(FULL, best, off);
                best = (o > best) ? o : best;
            }
            if ((tid & 31) == 0) warpmax[tid >> 5] = best;
            __syncthreads();
            if (tid == 0) {
                unsigned long long b = warpmax[0];
                for (int w = 1; w < 16; w++) b = (warpmax[w] > b) ? warpmax[w] : b;
                int idx = (int)(0xFFFFFFFFu - (unsigned)(b & 0xFFFFFFFFull));
                sel[k] = idx;
                skey[idx] = 0ull;
            }
            __syncthreads();
        }
        if (tid < K_KEYPTS * 6) {
            int k = tid / 6, c = tid % 6;
            out[k * 6 + c] = src_pts[c * N_PTS + sel[k]];
        }
        return;
    }

    // ===== group blocks =====
    float4* sp            = (float4*)dynsmem;                              // 64KB
    unsigned short* sidx  = (unsigned short*)(dynsmem + 65536);            // 8KB
    float4* stile         = (float4*)(dynsmem + 65536 + 8192);             // 2KB

    for (int i = tid; i < N_PTS; i += 512) { sp[i] = g_sp[i]; sidx[i] = (unsigned short)g_sidx[i]; }
    for (int i = tid; i < N_TILES; i += 512) stile[i] = g_tile[i];
    __syncthreads();

    int warp = tid >> 5;
    int lane = tid & 31;
    int m = (blockIdx.x - 1) * 16 + warp;    // 2208 * 16 == 35328

    float qx = cand[m * 3 + 0];
    float qy = cand[m * 3 + 1];
    float qz = cand[m * 3 + 2];
    float qq = __fadd_rn(__fadd_rn(__fmul_rn(qx, qx), __fmul_rn(qy, qy)), __fmul_rn(qz, qz));

    // ---- per-tile conservative lower bounds, packed (bound-bits | tile-id) ----
    unsigned key[4];
#pragma unroll
    for (int r = 0; r < 4; r++) {
        int t = r * 32 + lane;
        float4 T = stile[t];
        float dx = qx - T.x, dy = qy - T.y, dz = qz - T.z;
        float d2c = dx * dx + dy * dy + dz * dz;
        float dc = sqrtf(d2c);
        float b  = fmaxf(dc - T.w, 0.0f);
        float bnd = b * b;                            // >= 0
        // truncate low 8 mantissa bits (rounds DOWN for +floats => conservative)
        key[r] = (__float_as_uint(bnd) & 0xFFFFFF00u) | (unsigned)t;
    }

    // ---- bitonic sort of 128 keys: element index i = (r<<5) | lane, ascending ----
    // NOTE: sort order affects ONLY visit order / pruning efficiency below, never
    // correctness (each tile is independently bound-checked; no early break).
#pragma unroll
    for (int k = 2; k <= 128; k <<= 1) {
#pragma unroll
        for (int j = k >> 1; j > 0; j >>= 1) {
            if (j >= 32) {
                int rj = j >> 5;                      // 1 or 2
#pragma unroll
                for (int r = 0; r < 4; r++) {
                    int rp = r ^ rj;
                    if (r < rp) {
                        bool up = (((r << 5) & k) == 0);
                        unsigned a = key[r], b = key[rp];
                        unsigned lo = min(a, b), hi = max(a, b);
                        key[r]  = up ? lo : hi;
                        key[rp] = up ? hi : lo;
                    }
                }
            } else {
#pragma unroll
                for (int r = 0; r < 4; r++) {
                    unsigned v = key[r];
                    unsigned o = __shfl_xor_sync(FULL, v, j);
                    int i = (r << 5) | lane;
                    bool up = ((i & k) == 0);
                    bool isLow = ((lane & j) == 0);
                    key[r] = ((isLow == up) ? min(v, o) : max(v, o));
                }
            }
        }
    }

    // ---- streaming top-32: visit tiles in (approximately) ascending-bound order ----
    // 64-bit selection key = (orderable(sq) << 32) | orig_idx  => TOTAL order, no ties.
    // Selection is provably independent of visit order; each tile is skipped only if
    // its conservative bound exceeds the current threshold by an absolute margin that
    // dwarfs the expanded-formula cancellation error. No sortedness assumption.
    const unsigned long long INITK = 0xFFFFFFFFFFFFFFFFull;
    unsigned long long bk = INITK;   // lane-sorted ascending; lane 31 = worst kept
    int bi = 0;                      // permuted position matching bk
    unsigned long long thrk = INITK; // == bk at lane 31, replicated

#pragma unroll
    for (int r = 0; r < 4; r++) {
        for (int ls = 0; ls < 32; ls++) {
            unsigned kk = __shfl_sync(FULL, key[r], ls);
            float bnd = __uint_as_float(kk & 0xFFFFFF00u);
            // threshold distance from key's high 32 bits (inverse order transform)
            unsigned uh = (unsigned)(thrk >> 32);
            float thr_d = __uint_as_float((uh & 0x80000000u) ? (uh ^ 0x80000000u) : ~uh);
            float limit = fminf(thr_d, RADIUS2);   // fminf(NaN, R2) = R2 when list not full
            if (bnd > limit + 0.01f) continue;     // SAFE skip: tile provably empty of admissible pts
            int t = (int)(kk & 0xFFu);

            float4 P = sp[t * 32 + lane];
            float dot = fmaf(qz, P.z, fmaf(qy, P.y, __fmul_rn(qx, P.x)));
            float sq  = __fadd_rn(__fsub_rn(qq, __fmul_rn(2.0f, dot)), P.w);
            unsigned u = __float_as_uint(sq);
            u = (u & 0x80000000u) ? ~u : (u | 0x80000000u);
            unsigned orig = (unsigned)sidx[t * 32 + lane];
            unsigned long long k64 = ((unsigned long long)u << 32) | orig;

            bool ok = (sq <= RADIUS2) && (k64 < thrk);
            unsigned mask = __ballot_sync(FULL, ok);
            while (mask) {
                int s = __ffs(mask) - 1;
                mask &= mask - 1;
                unsigned long long kc = __shfl_sync(FULL, k64, s);
                if (kc < thrk) {                     // warp-uniform
                    int ic = t * 32 + s;
                    unsigned long long pk = __shfl_up_sync(FULL, bk, 1);
                    int pi = __shfl_up_sync(FULL, bi, 1);
                    if (bk > kc) {                   // shift-insert; lane 31 falls off
                        bool take = (lane == 0) || (pk <= kc);
                        bk = take ? kc : pk;
                        bi = take ? ic : pi;
                    }
                    thrk = __shfl_sync(FULL, bk, 31);
                }
            }
        }
    }

    // padding: invalid slots take slot-0's index; if no valid neighbor -> original index 0
    int nv  = __popc(__ballot_sync(FULL, bk != INITK));   // admitted => sq <= RADIUS2
    int bi0 = __shfl_sync(FULL, bi, 0);
    int fidx;
    if (nv > 0) {
        fidx = (lane < nv) ? bi : bi0;
    } else {
        fidx = g_pos0;                 // permuted position of original point 0
    }

    // coalesced write of 32*35 = 1120 floats per query
    float* op = out + OUT_GROUP_OFF + (size_t)m * (NSAMPLE * 35);
    int slot = 0, t35 = lane;
#pragma unroll 1
    for (int it = 0; it < 35; it++) {
        int is = __shfl_sync(FULL, fidx, slot);
        float val;
        if (t35 < 3) {
            float4 P = sp[is];
            float pc = (t35 == 0) ? P.x : ((t35 == 1) ? P.y : P.z);
            float qc = (t35 == 0) ? qx  : ((t35 == 1) ? qy  : qz);
            val = __fsub_rn(pc, qc);
        } else {
            int orig = (int)sidx[is];
            val = g_feat[orig * FEAT_D + (t35 - 3)];
        }
        op[it * 32 + lane] = val;
        t35 += 32;
        if (t35 >= 35) { t35 -= 35; slot++; }
    }
}

// ---------------- launch ----------------
extern "C" void kernel_launch(void* const* d_in, const int* in_sizes, int n_in,
                              void* d_out, int out_size)
{
    const float* src  = (const float*)d_in[0];
    const float* tgt  = (const float*)d_in[1];
    const float* cand = (const float*)d_in[2];
    const float* W1   = (const float*)d_in[3];
    const float* b1   = (const float*)d_in[4];
    const float* W2   = (const float*)d_in[5];
    const float* b2   = (const float*)d_in[6];
    const float* Wq   = (const float*)d_in[7];
    const float* bq   = (const float*)d_in[8];
    float* out = (float*)d_out;

    const int GROUP_SMEM = 65536 + 8192 + 2048;   // 75776

    static bool s_attr_done = false;
    if (!s_attr_done) {
        cudaFuncSetAttribute(group_kernel, cudaFuncAttributeMaxDynamicSharedMemorySize, GROUP_SMEM);
        s_attr_done = true;
    }

    mlp_kernel<<<dim3(32, 2), 128>>>(src, tgt, W1, b1, W2, b2, Wq, bq);
    sortstats_kernel<<<1, 1024>>>(tgt);
    group_kernel<<<1 + N_QUERY / 16, 512, GROUP_SMEM>>>(cand, src, out);
}